// round 7
// baseline (speedup 1.0000x reference)
#include <cuda_runtime.h>
#include <math.h>

// Fixed problem shape (from reference_code)
#define MAXN 50000
#define MAXE 800000
#define FIN  128
#define FH   128
#define FOUT 40

// ---------------- device scratch (no allocations allowed) ----------------
__device__ __align__(16) float g_h[MAXN * FH];   // GEMM output (also 40-wide h)
__device__ __align__(16) float g_x[MAXN * FH];   // layer activations
__device__ float g_dinv[MAXN];
__device__ int   g_cnt[MAXN];
__device__ int   g_rowptr[MAXN + 1];
__device__ int   g_cursor[MAXN];
__device__ int   g_col[MAXE];
__device__ float g_w[MAXE];
__device__ int   g_mode;     // 0=int64, 1=int32, 2=float32, 3=float64
#define SCAN_B 256
#define MAX_BLKS ((MAXN + SCAN_B - 1) / SCAN_B)   // 196
__device__ int   g_bsum[MAX_BLKS];
__device__ int   g_boff[MAX_BLKS];

// ---------------- edge index access, dispatched on detected dtype -------
__device__ __forceinline__ int edge_at(const void* p, int idx, int mode) {
    switch (mode) {
        case 0:  return (int)((const long long*)p)[idx];
        case 1:  return ((const int*)p)[idx];
        case 2:  return (int)((const float*)p)[idx];
        default: return (int)((const double*)p)[idx];
    }
}

// ---------------- prep kernels ----------------
__global__ void zero_cnt_kernel(int n) {
    int i = blockIdx.x * blockDim.x + threadIdx.x;
    if (i < n) g_cnt[i] = 0;
}

// ONE block, sampled dtype detection (no global atomics).
//  int64  : hi words all zero;  float64: lo words all zero;
//  int32  : every word < n;     else float32.
__global__ void detect_kernel(const unsigned* __restrict__ w, int E, int n) {
    __shared__ int sh[3];
    int t = threadIdx.x;
    unsigned oddnz = 0, evennz = 0, bigint = 0;
    int nsamp = (E < 4096) ? E : 4096;
    for (int k = t; k < nsamp; k += 256) {
        unsigned lo = w[2 * k];
        unsigned hi = w[2 * k + 1];
        oddnz  |= hi;
        evennz |= lo;
        bigint |= (lo >= (unsigned)n || hi >= (unsigned)n) ? 1u : 0u;
    }
    // warp-level OR-reduce, then cross-warp via shared
    unsigned o = __any_sync(0xFFFFFFFFu, oddnz != 0);
    unsigned ev = __any_sync(0xFFFFFFFFu, evennz != 0);
    unsigned bg = __any_sync(0xFFFFFFFFu, bigint != 0);
    if (t == 0) { sh[0] = 0; sh[1] = 0; sh[2] = 0; }
    __syncthreads();
    if ((t & 31) == 0) {
        if (o)  atomicOr(&sh[0], 1);
        if (ev) atomicOr(&sh[1], 1);
        if (bg) atomicOr(&sh[2], 1);
    }
    __syncthreads();
    if (t == 0) {
        if (!sh[0])      g_mode = 0;   // int64
        else if (!sh[1]) g_mode = 3;   // float64
        else if (!sh[2]) g_mode = 1;   // int32
        else             g_mode = 2;   // float32
    }
}

__global__ void count_kernel(const void* __restrict__ edges, int E, int n) {
    int i = blockIdx.x * blockDim.x + threadIdx.x;
    if (i < E) {
        int d = edge_at(edges, E + i, g_mode);
        if ((unsigned)d < (unsigned)n) atomicAdd(&g_cnt[d], 1);
    }
}

__global__ void dinv_kernel(int n) {
    int i = blockIdx.x * blockDim.x + threadIdx.x;
    if (i < n) g_dinv[i] = rsqrtf((float)(g_cnt[i] + 1));  // +1 self-loop
}

// ---- hierarchical exclusive scan: A) block sums, B) scan sums, C) local --
__global__ void scanA_kernel(int n) {
    __shared__ int sh[SCAN_B];
    int t = threadIdx.x;
    int i = blockIdx.x * SCAN_B + t;
    int v = (i < n) ? g_cnt[i] : 0;
    sh[t] = v;
    __syncthreads();
    for (int off = SCAN_B / 2; off > 0; off >>= 1) {
        if (t < off) sh[t] += sh[t + off];
        __syncthreads();
    }
    if (t == 0) g_bsum[blockIdx.x] = sh[0];
}

__global__ void scanB_kernel(int nb, int n) {
    __shared__ int sh[SCAN_B];
    int t = threadIdx.x;
    int v = (t < nb) ? g_bsum[t] : 0;
    sh[t] = v;
    __syncthreads();
    for (int off = 1; off < SCAN_B; off <<= 1) {
        int add = (t >= off) ? sh[t - off] : 0;
        __syncthreads();
        sh[t] += add;
        __syncthreads();
    }
    if (t < nb) g_boff[t] = sh[t] - v;       // exclusive
    if (t == SCAN_B - 1) g_rowptr[n] = sh[SCAN_B - 1];  // total
}

__global__ void scanC_kernel(int n) {
    __shared__ int sh[SCAN_B];
    int t = threadIdx.x;
    int i = blockIdx.x * SCAN_B + t;
    int v = (i < n) ? g_cnt[i] : 0;
    sh[t] = v;
    __syncthreads();
    for (int off = 1; off < SCAN_B; off <<= 1) {
        int add = (t >= off) ? sh[t - off] : 0;
        __syncthreads();
        sh[t] += add;
        __syncthreads();
    }
    if (i < n) {
        int excl = g_boff[blockIdx.x] + sh[t] - v;
        g_rowptr[i] = excl;
        g_cursor[i] = excl;
    }
}

__global__ void fill_kernel(const void* __restrict__ edges, int E, int n) {
    int i = blockIdx.x * blockDim.x + threadIdx.x;
    if (i < E) {
        int mode = g_mode;
        int s = edge_at(edges, i, mode);
        int d = edge_at(edges, E + i, mode);
        if ((unsigned)s < (unsigned)n && (unsigned)d < (unsigned)n) {
            int pos = atomicAdd(&g_cursor[d], 1);
            g_col[pos] = s;
            g_w[pos] = g_dinv[s] * g_dinv[d];
        }
    }
}

// ---------------- GEMM: g_h[n,128] = X[n,128] @ W[128,128] ----------------
#define XP 36
#define WP 132
__global__ __launch_bounds__(256) void gemm128_kernel(
    const float* __restrict__ Xext, const float* __restrict__ W,
    int src_sel, int n)
{
    __shared__ float sX[128 * XP];
    __shared__ float sW[32 * WP];

    const float* X = src_sel ? (const float*)g_x : Xext;

    int tid = threadIdx.x;
    int row0 = blockIdx.x * 128;

    int ty = tid >> 4;
    int tx = tid & 15;
    int r0 = ty * 8;
    int c0 = tx * 4;

    float acc[8][8];
#pragma unroll
    for (int i = 0; i < 8; i++)
#pragma unroll
        for (int j = 0; j < 8; j++) acc[i][j] = 0.0f;

    for (int k0 = 0; k0 < 128; k0 += 32) {
#pragma unroll
        for (int l = 0; l < 16; l++) {
            int idx = l * 256 + tid;
            int k = idx & 31;
            int r = idx >> 5;
            int row = row0 + r;
            sX[r * XP + k] = (row < n) ? X[row * 128 + k0 + k] : 0.0f;
        }
#pragma unroll
        for (int l = 0; l < 16; l++) {
            int idx = l * 256 + tid;
            int c = idx & 127;
            int k = idx >> 7;
            sW[k * WP + c] = W[(k0 + k) * 128 + c];
        }
        __syncthreads();

#pragma unroll
        for (int k = 0; k < 32; k++) {
            float xv[8];
#pragma unroll
            for (int i = 0; i < 8; i++) xv[i] = sX[(r0 + i) * XP + k];
            float4 wa = *(const float4*)&sW[k * WP + c0];
            float4 wb = *(const float4*)&sW[k * WP + 64 + c0];
#pragma unroll
            for (int i = 0; i < 8; i++) {
                acc[i][0] += xv[i] * wa.x; acc[i][1] += xv[i] * wa.y;
                acc[i][2] += xv[i] * wa.z; acc[i][3] += xv[i] * wa.w;
                acc[i][4] += xv[i] * wb.x; acc[i][5] += xv[i] * wb.y;
                acc[i][6] += xv[i] * wb.z; acc[i][7] += xv[i] * wb.w;
            }
        }
        __syncthreads();
    }

#pragma unroll
    for (int i = 0; i < 8; i++) {
        int row = row0 + r0 + i;
        if (row < n) {
            *(float4*)&g_h[row * 128 + c0] =
                make_float4(acc[i][0], acc[i][1], acc[i][2], acc[i][3]);
            *(float4*)&g_h[row * 128 + 64 + c0] =
                make_float4(acc[i][4], acc[i][5], acc[i][6], acc[i][7]);
        }
    }
}

// ---------------- GEMM: g_h[n,40] = g_x[n,128] @ W[128,40] ----------------
#define XPAD 132
__global__ __launch_bounds__(256) void gemm40_kernel(
    const float* __restrict__ W, int n)
{
    __shared__ float sW[128 * 40];
    __shared__ float sX[32 * XPAD];

    int tid = threadIdx.x;
    int row0 = blockIdx.x * 32;

    for (int idx = tid; idx < 128 * 40; idx += 256) sW[idx] = W[idx];
    for (int idx = tid; idx < 32 * 128; idx += 256) {
        int r = idx >> 7;
        int k = idx & 127;
        int row = row0 + r;
        sX[r * XPAD + k] = (row < n) ? g_x[row * 128 + k] : 0.0f;
    }
    __syncthreads();

    int ty = tid >> 3;
    int tx = tid & 7;
    int c0 = tx * 5;

    float acc[5] = {0, 0, 0, 0, 0};
#pragma unroll 4
    for (int k = 0; k < 128; k++) {
        float xv = sX[ty * XPAD + k];
#pragma unroll
        for (int j = 0; j < 5; j++) acc[j] += xv * sW[k * 40 + c0 + j];
    }

    int row = row0 + ty;
    if (row < n) {
#pragma unroll
        for (int j = 0; j < 5; j++) g_h[row * 40 + c0 + j] = acc[j];
    }
}

// -------- aggregation (128-dim): warp/node, float4 lanes, MLP=4 --------
__global__ __launch_bounds__(256) void agg128_kernel(
    const float* __restrict__ b, int n)
{
    int warp = threadIdx.x >> 5;
    int lane = threadIdx.x & 31;
    int i = blockIdx.x * 8 + warp;
    if (i >= n) return;

    const float4* __restrict__ h4 = (const float4*)g_h;
    float4* x4 = (float4*)g_x;
    const float4* b4 = (const float4*)b;

    float di = g_dinv[i];
    float self_w = di * di;
    float4 hv = h4[i * 32 + lane];
    float ax = hv.x * self_w, ay = hv.y * self_w;
    float az = hv.z * self_w, aw = hv.w * self_w;

    int s = g_rowptr[i];
    int e = g_rowptr[i + 1];
    int j = s;
    for (; j + 4 <= e; j += 4) {
        int   c0 = g_col[j],   c1 = g_col[j+1], c2 = g_col[j+2], c3 = g_col[j+3];
        float w0 = g_w[j],     w1 = g_w[j+1],   w2 = g_w[j+2],   w3 = g_w[j+3];
        float4 v0 = h4[c0 * 32 + lane];
        float4 v1 = h4[c1 * 32 + lane];
        float4 v2 = h4[c2 * 32 + lane];
        float4 v3 = h4[c3 * 32 + lane];
        ax += w0*v0.x + w1*v1.x + w2*v2.x + w3*v3.x;
        ay += w0*v0.y + w1*v1.y + w2*v2.y + w3*v3.y;
        az += w0*v0.z + w1*v1.z + w2*v2.z + w3*v3.z;
        aw += w0*v0.w + w1*v1.w + w2*v2.w + w3*v3.w;
    }
    for (; j < e; j++) {
        int c = g_col[j];
        float wt = g_w[j];
        float4 v = h4[c * 32 + lane];
        ax += wt * v.x; ay += wt * v.y; az += wt * v.z; aw += wt * v.w;
    }
    float4 bv = b4[lane];
    float4 o;
    o.x = fmaxf(ax + bv.x, 0.0f);
    o.y = fmaxf(ay + bv.y, 0.0f);
    o.z = fmaxf(az + bv.z, 0.0f);
    o.w = fmaxf(aw + bv.w, 0.0f);
    x4[i * 32 + lane] = o;
}

// ---------------- final: agg(40) + bias + relu + log_softmax -> out ----
__global__ __launch_bounds__(256) void agg40_lsm_kernel(
    const float* __restrict__ b, float* __restrict__ out, int n)
{
    int warp = threadIdx.x >> 5;
    int lane = threadIdx.x & 31;
    int i = blockIdx.x * 8 + warp;
    if (i >= n) return;

    float y0 = -INFINITY, y1 = -INFINITY;
    bool active = (lane < 20);
    int c0 = lane * 2;

    if (active) {
        float di = g_dinv[i];
        float self_w = di * di;
        const float2* __restrict__ h2 = (const float2*)g_h;
        float2 hv = h2[i * 20 + lane];
        float a0 = hv.x * self_w;
        float a1 = hv.y * self_w;
        int s = g_rowptr[i];
        int e = g_rowptr[i + 1];
        int j = s;
        for (; j + 4 <= e; j += 4) {
            int   cc0 = g_col[j],   cc1 = g_col[j+1];
            int   cc2 = g_col[j+2], cc3 = g_col[j+3];
            float w0 = g_w[j],   w1 = g_w[j+1];
            float w2 = g_w[j+2], w3 = g_w[j+3];
            float2 v0 = h2[cc0 * 20 + lane];
            float2 v1 = h2[cc1 * 20 + lane];
            float2 v2 = h2[cc2 * 20 + lane];
            float2 v3 = h2[cc3 * 20 + lane];
            a0 += w0*v0.x + w1*v1.x + w2*v2.x + w3*v3.x;
            a1 += w0*v0.y + w1*v1.y + w2*v2.y + w3*v3.y;
        }
        for (; j < e; j++) {
            int c = g_col[j];
            float wt = g_w[j];
            float2 v = h2[c * 20 + lane];
            a0 += wt * v.x;
            a1 += wt * v.y;
        }
        y0 = fmaxf(a0 + b[c0], 0.0f);
        y1 = fmaxf(a1 + b[c0 + 1], 0.0f);
    }

    float m = fmaxf(y0, y1);
#pragma unroll
    for (int off = 16; off > 0; off >>= 1)
        m = fmaxf(m, __shfl_xor_sync(0xFFFFFFFFu, m, off));

    float se = active ? (expf(y0 - m) + expf(y1 - m)) : 0.0f;
#pragma unroll
    for (int off = 16; off > 0; off >>= 1)
        se += __shfl_xor_sync(0xFFFFFFFFu, se, off);

    float lse = m + logf(se);
    if (active) {
        out[i * 40 + c0]     = y0 - lse;
        out[i * 40 + c0 + 1] = y1 - lse;
    }
}

// ---------------- launch (kernel launches ONLY — capture-safe; ----------
// ---------------- NO __device__ symbol is referenced from host) ---------
extern "C" void kernel_launch(void* const* d_in, const int* in_sizes, int n_in,
                              void* d_out, int out_size) {
    const float* x  = (const float*)d_in[0];
    const void*  ei = d_in[1];
    const float* W0 = (const float*)d_in[2];
    const float* b0 = (const float*)d_in[3];
    const float* W1 = (const float*)d_in[4];
    const float* b1 = (const float*)d_in[5];
    const float* W2 = (const float*)d_in[6];
    const float* b2 = (const float*)d_in[7];
    float* out = (float*)d_out;

    int n = in_sizes[0] / FIN;      // 50000
    int E = in_sizes[1] / 2;        // 800000

    const int TB = 256;
    int gN = (n + TB - 1) / TB;
    int gE = (E + TB - 1) / TB;
    int nb = (n + SCAN_B - 1) / SCAN_B;
    int gWarp8 = (n + 7) / 8;
    int gGemm128 = (n + 127) / 128;
    int gGemm40  = (n + 31) / 32;

    // --- graph prep (recomputed every replay; deterministic work) ---
    zero_cnt_kernel<<<gN, TB>>>(n);
    detect_kernel<<<1, 256>>>((const unsigned*)ei, E, n);
    count_kernel<<<gE, TB>>>(ei, E, n);
    dinv_kernel<<<gN, TB>>>(n);
    scanA_kernel<<<nb, SCAN_B>>>(n);
    scanB_kernel<<<1, SCAN_B>>>(nb, n);
    scanC_kernel<<<nb, SCAN_B>>>(n);
    fill_kernel<<<gE, TB>>>(ei, E, n);

    // --- layer 0 ---
    gemm128_kernel<<<gGemm128, 256>>>(x, W0, 0, n);
    agg128_kernel<<<gWarp8, 256>>>(b0, n);
    // --- layer 1 (input = g_x, selected in device code) ---
    gemm128_kernel<<<gGemm128, 256>>>(x, W1, 1, n);
    agg128_kernel<<<gWarp8, 256>>>(b1, n);
    // --- layer 2 + log_softmax ---
    gemm40_kernel<<<gGemm40, 256>>>(W2, n);
    agg40_lsm_kernel<<<gWarp8, 256>>>(b2, out, n);
}

// round 8
// speedup vs baseline: 1.6027x; 1.6027x over previous
#include <cuda_runtime.h>
#include <cuda_fp16.h>
#include <math.h>

// Fixed problem shape (from reference_code)
#define MAXN 50000
#define MAXE 800000
#define FIN  128
#define FH   128
#define FOUT 40

// ---------------- device scratch (no allocations allowed) ----------------
__device__ __align__(16) float  g_h[MAXN * FH];    // fp32 h (layer 2 path)
__device__ __align__(16) __half g_hh[MAXN * FH];   // fp16 h (layers 0/1 agg)
__device__ __align__(16) float  g_x[MAXN * FH];    // layer activations
__device__ float g_dinv[MAXN];
__device__ int   g_cnt[MAXN];
__device__ int   g_rowptr[MAXN + 1];
__device__ int   g_cursor[MAXN];
__device__ int   g_col[MAXE];
__device__ float g_w[MAXE];
__device__ int   g_mode;     // 0=int64, 1=int32, 2=float32, 3=float64
#define SCAN_B 256
#define MAX_BLKS ((MAXN + SCAN_B - 1) / SCAN_B)   // 196
__device__ int   g_bsum[MAX_BLKS];
__device__ int   g_boff[MAX_BLKS];

// ---------------- edge index access, dispatched on detected dtype -------
__device__ __forceinline__ int edge_at(const void* p, int idx, int mode) {
    switch (mode) {
        case 0:  return (int)((const long long*)p)[idx];
        case 1:  return ((const int*)p)[idx];
        case 2:  return (int)((const float*)p)[idx];
        default: return (int)((const double*)p)[idx];
    }
}

// ---------------- prep kernels ----------------
__global__ void zero_cnt_kernel(int n) {
    int i = blockIdx.x * blockDim.x + threadIdx.x;
    if (i < n) g_cnt[i] = 0;
}

// ONE block, sampled dtype detection (no global atomics).
__global__ void detect_kernel(const unsigned* __restrict__ w, int E, int n) {
    __shared__ int sh[3];
    int t = threadIdx.x;
    unsigned oddnz = 0, evennz = 0, bigint = 0;
    int nsamp = (E < 4096) ? E : 4096;
    for (int k = t; k < nsamp; k += 256) {
        unsigned lo = w[2 * k];
        unsigned hi = w[2 * k + 1];
        oddnz  |= hi;
        evennz |= lo;
        bigint |= (lo >= (unsigned)n || hi >= (unsigned)n) ? 1u : 0u;
    }
    unsigned o  = __any_sync(0xFFFFFFFFu, oddnz != 0);
    unsigned ev = __any_sync(0xFFFFFFFFu, evennz != 0);
    unsigned bg = __any_sync(0xFFFFFFFFu, bigint != 0);
    if (t == 0) { sh[0] = 0; sh[1] = 0; sh[2] = 0; }
    __syncthreads();
    if ((t & 31) == 0) {
        if (o)  atomicOr(&sh[0], 1);
        if (ev) atomicOr(&sh[1], 1);
        if (bg) atomicOr(&sh[2], 1);
    }
    __syncthreads();
    if (t == 0) {
        if (!sh[0])      g_mode = 0;   // int64
        else if (!sh[1]) g_mode = 3;   // float64
        else if (!sh[2]) g_mode = 1;   // int32
        else             g_mode = 2;   // float32
    }
}

__global__ void count_kernel(const void* __restrict__ edges, int E, int n) {
    int i = blockIdx.x * blockDim.x + threadIdx.x;
    if (i < E) {
        int d = edge_at(edges, E + i, g_mode);
        if ((unsigned)d < (unsigned)n) atomicAdd(&g_cnt[d], 1);
    }
}

__global__ void dinv_kernel(int n) {
    int i = blockIdx.x * blockDim.x + threadIdx.x;
    if (i < n) g_dinv[i] = rsqrtf((float)(g_cnt[i] + 1));  // +1 self-loop
}

// ---- hierarchical exclusive scan: A) block sums, B) scan sums, C) local --
__global__ void scanA_kernel(int n) {
    __shared__ int sh[SCAN_B];
    int t = threadIdx.x;
    int i = blockIdx.x * SCAN_B + t;
    int v = (i < n) ? g_cnt[i] : 0;
    sh[t] = v;
    __syncthreads();
    for (int off = SCAN_B / 2; off > 0; off >>= 1) {
        if (t < off) sh[t] += sh[t + off];
        __syncthreads();
    }
    if (t == 0) g_bsum[blockIdx.x] = sh[0];
}

__global__ void scanB_kernel(int nb, int n) {
    __shared__ int sh[SCAN_B];
    int t = threadIdx.x;
    int v = (t < nb) ? g_bsum[t] : 0;
    sh[t] = v;
    __syncthreads();
    for (int off = 1; off < SCAN_B; off <<= 1) {
        int add = (t >= off) ? sh[t - off] : 0;
        __syncthreads();
        sh[t] += add;
        __syncthreads();
    }
    if (t < nb) g_boff[t] = sh[t] - v;       // exclusive
    if (t == SCAN_B - 1) g_rowptr[n] = sh[SCAN_B - 1];  // total
}

__global__ void scanC_kernel(int n) {
    __shared__ int sh[SCAN_B];
    int t = threadIdx.x;
    int i = blockIdx.x * SCAN_B + t;
    int v = (i < n) ? g_cnt[i] : 0;
    sh[t] = v;
    __syncthreads();
    for (int off = 1; off < SCAN_B; off <<= 1) {
        int add = (t >= off) ? sh[t - off] : 0;
        __syncthreads();
        sh[t] += add;
        __syncthreads();
    }
    if (i < n) {
        int excl = g_boff[blockIdx.x] + sh[t] - v;
        g_rowptr[i] = excl;
        g_cursor[i] = excl;
    }
}

__global__ void fill_kernel(const void* __restrict__ edges, int E, int n) {
    int i = blockIdx.x * blockDim.x + threadIdx.x;
    if (i < E) {
        int mode = g_mode;
        int s = edge_at(edges, i, mode);
        int d = edge_at(edges, E + i, mode);
        if ((unsigned)s < (unsigned)n && (unsigned)d < (unsigned)n) {
            int pos = atomicAdd(&g_cursor[d], 1);
            g_col[pos] = s;
            g_w[pos] = g_dinv[s] * g_dinv[d];
        }
    }
}

// ---------------- GEMM: g_hh[n,128] = fp16( X[n,128] @ W[128,128] ) ------
#define XP 36
#define WP 132
__global__ __launch_bounds__(256) void gemm128_kernel(
    const float* __restrict__ Xext, const float* __restrict__ W,
    int src_sel, int n)
{
    __shared__ float sX[128 * XP];
    __shared__ float sW[32 * WP];

    const float* X = src_sel ? (const float*)g_x : Xext;

    int tid = threadIdx.x;
    int row0 = blockIdx.x * 128;

    int ty = tid >> 4;
    int tx = tid & 15;
    int r0 = ty * 8;
    int c0 = tx * 4;

    float acc[8][8];
#pragma unroll
    for (int i = 0; i < 8; i++)
#pragma unroll
        for (int j = 0; j < 8; j++) acc[i][j] = 0.0f;

    for (int k0 = 0; k0 < 128; k0 += 32) {
#pragma unroll
        for (int l = 0; l < 16; l++) {
            int idx = l * 256 + tid;
            int k = idx & 31;
            int r = idx >> 5;
            int row = row0 + r;
            sX[r * XP + k] = (row < n) ? X[row * 128 + k0 + k] : 0.0f;
        }
#pragma unroll
        for (int l = 0; l < 16; l++) {
            int idx = l * 256 + tid;
            int c = idx & 127;
            int k = idx >> 7;
            sW[k * WP + c] = W[(k0 + k) * 128 + c];
        }
        __syncthreads();

#pragma unroll
        for (int k = 0; k < 32; k++) {
            float xv[8];
#pragma unroll
            for (int i = 0; i < 8; i++) xv[i] = sX[(r0 + i) * XP + k];
            float4 wa = *(const float4*)&sW[k * WP + c0];
            float4 wb = *(const float4*)&sW[k * WP + 64 + c0];
#pragma unroll
            for (int i = 0; i < 8; i++) {
                acc[i][0] += xv[i] * wa.x; acc[i][1] += xv[i] * wa.y;
                acc[i][2] += xv[i] * wa.z; acc[i][3] += xv[i] * wa.w;
                acc[i][4] += xv[i] * wb.x; acc[i][5] += xv[i] * wb.y;
                acc[i][6] += xv[i] * wb.z; acc[i][7] += xv[i] * wb.w;
            }
        }
        __syncthreads();
    }

    __half2* hh2 = (__half2*)g_hh;
#pragma unroll
    for (int i = 0; i < 8; i++) {
        int row = row0 + r0 + i;
        if (row < n) {
            // cols [c0, c0+4) and [64+c0, 64+c0+4) as half2 pairs
            hh2[row * 64 + (c0 >> 1)] =
                __floats2half2_rn(acc[i][0], acc[i][1]);
            hh2[row * 64 + (c0 >> 1) + 1] =
                __floats2half2_rn(acc[i][2], acc[i][3]);
            hh2[row * 64 + 32 + (c0 >> 1)] =
                __floats2half2_rn(acc[i][4], acc[i][5]);
            hh2[row * 64 + 32 + (c0 >> 1) + 1] =
                __floats2half2_rn(acc[i][6], acc[i][7]);
        }
    }
}

// ---------------- GEMM: g_h[n,40] = g_x[n,128] @ W[128,40] (fp32) --------
#define XPAD 132
__global__ __launch_bounds__(256) void gemm40_kernel(
    const float* __restrict__ W, int n)
{
    __shared__ float sW[128 * 40];
    __shared__ float sX[32 * XPAD];

    int tid = threadIdx.x;
    int row0 = blockIdx.x * 32;

    for (int idx = tid; idx < 128 * 40; idx += 256) sW[idx] = W[idx];
    for (int idx = tid; idx < 32 * 128; idx += 256) {
        int r = idx >> 7;
        int k = idx & 127;
        int row = row0 + r;
        sX[r * XPAD + k] = (row < n) ? g_x[row * 128 + k] : 0.0f;
    }
    __syncthreads();

    int ty = tid >> 3;
    int tx = tid & 7;
    int c0 = tx * 5;

    float acc[5] = {0, 0, 0, 0, 0};
#pragma unroll 4
    for (int k = 0; k < 128; k++) {
        float xv = sX[ty * XPAD + k];
#pragma unroll
        for (int j = 0; j < 5; j++) acc[j] += xv * sW[k * 40 + c0 + j];
    }

    int row = row0 + ty;
    if (row < n) {
#pragma unroll
        for (int j = 0; j < 5; j++) g_h[row * 40 + c0 + j] = acc[j];
    }
}

// ---- aggregation (128-dim): warp/node, fp16 gather (8B/lane/edge) ------
// g_x = relu( A_norm @ h + b ), fp32 accumulate
__global__ __launch_bounds__(128) void agg128_kernel(
    const float* __restrict__ b, int n)
{
    int warp = threadIdx.x >> 5;
    int lane = threadIdx.x & 31;
    int i = blockIdx.x * 4 + warp;
    if (i >= n) return;

    const uint2* __restrict__ hq = (const uint2*)g_hh;  // 4 halves per lane
    float4* x4 = (float4*)g_x;
    const float4* b4 = (const float4*)b;

    float di = g_dinv[i];
    float self_w = di * di;

    uint2 qs = hq[i * 32 + lane];
    float2 s0 = __half22float2(*(const __half2*)&qs.x);
    float2 s1 = __half22float2(*(const __half2*)&qs.y);
    float ax = s0.x * self_w, ay = s0.y * self_w;
    float az = s1.x * self_w, aw = s1.y * self_w;

    int s = g_rowptr[i];
    int e = g_rowptr[i + 1];
    for (int j = s; j < e; j++) {
        int c = g_col[j];
        float wt = g_w[j];
        uint2 q = hq[c * 32 + lane];
        float2 f0 = __half22float2(*(const __half2*)&q.x);
        float2 f1 = __half22float2(*(const __half2*)&q.y);
        ax += wt * f0.x; ay += wt * f0.y;
        az += wt * f1.x; aw += wt * f1.y;
    }
    float4 bv = b4[lane];
    float4 o;
    o.x = fmaxf(ax + bv.x, 0.0f);
    o.y = fmaxf(ay + bv.y, 0.0f);
    o.z = fmaxf(az + bv.z, 0.0f);
    o.w = fmaxf(aw + bv.w, 0.0f);
    x4[i * 32 + lane] = o;
}

// ---------------- final: agg(40) + bias + relu + log_softmax -> out ----
__global__ __launch_bounds__(128) void agg40_lsm_kernel(
    const float* __restrict__ b, float* __restrict__ out, int n)
{
    int warp = threadIdx.x >> 5;
    int lane = threadIdx.x & 31;
    int i = blockIdx.x * 4 + warp;
    if (i >= n) return;

    float y0 = -INFINITY, y1 = -INFINITY;
    bool active = (lane < 20);
    int c0 = lane * 2;

    if (active) {
        float di = g_dinv[i];
        float self_w = di * di;
        const float2* __restrict__ h2 = (const float2*)g_h;
        float2 hv = h2[i * 20 + lane];
        float a0 = hv.x * self_w;
        float a1 = hv.y * self_w;
        int s = g_rowptr[i];
        int e = g_rowptr[i + 1];
        for (int j = s; j < e; j++) {
            int c = g_col[j];
            float wt = g_w[j];
            float2 v = h2[c * 20 + lane];
            a0 += wt * v.x;
            a1 += wt * v.y;
        }
        y0 = fmaxf(a0 + b[c0], 0.0f);
        y1 = fmaxf(a1 + b[c0 + 1], 0.0f);
    }

    float m = fmaxf(y0, y1);
#pragma unroll
    for (int off = 16; off > 0; off >>= 1)
        m = fmaxf(m, __shfl_xor_sync(0xFFFFFFFFu, m, off));

    float se = active ? (expf(y0 - m) + expf(y1 - m)) : 0.0f;
#pragma unroll
    for (int off = 16; off > 0; off >>= 1)
        se += __shfl_xor_sync(0xFFFFFFFFu, se, off);

    float lse = m + logf(se);
    if (active) {
        out[i * 40 + c0]     = y0 - lse;
        out[i * 40 + c0 + 1] = y1 - lse;
    }
}

// ---------------- launch (kernel launches ONLY — capture-safe; ----------
// ---------------- NO __device__ symbol is referenced from host) ---------
extern "C" void kernel_launch(void* const* d_in, const int* in_sizes, int n_in,
                              void* d_out, int out_size) {
    const float* x  = (const float*)d_in[0];
    const void*  ei = d_in[1];
    const float* W0 = (const float*)d_in[2];
    const float* b0 = (const float*)d_in[3];
    const float* W1 = (const float*)d_in[4];
    const float* b1 = (const float*)d_in[5];
    const float* W2 = (const float*)d_in[6];
    const float* b2 = (const float*)d_in[7];
    float* out = (float*)d_out;

    int n = in_sizes[0] / FIN;      // 50000
    int E = in_sizes[1] / 2;        // 800000

    const int TB = 256;
    int gN = (n + TB - 1) / TB;
    int gE = (E + TB - 1) / TB;
    int nb = (n + SCAN_B - 1) / SCAN_B;
    int gWarp = (n + 3) / 4;
    int gGemm128 = (n + 127) / 128;
    int gGemm40  = (n + 31) / 32;

    // --- graph prep (recomputed every replay; deterministic work) ---
    zero_cnt_kernel<<<gN, TB>>>(n);
    detect_kernel<<<1, 256>>>((const unsigned*)ei, E, n);
    count_kernel<<<gE, TB>>>(ei, E, n);
    dinv_kernel<<<gN, TB>>>(n);
    scanA_kernel<<<nb, SCAN_B>>>(n);
    scanB_kernel<<<1, SCAN_B>>>(nb, n);
    scanC_kernel<<<nb, SCAN_B>>>(n);
    fill_kernel<<<gE, TB>>>(ei, E, n);

    // --- layer 0 ---
    gemm128_kernel<<<gGemm128, 256>>>(x, W0, 0, n);
    agg128_kernel<<<gWarp, 128>>>(b0, n);
    // --- layer 1 (input = g_x, selected in device code) ---
    gemm128_kernel<<<gGemm128, 256>>>(x, W1, 1, n);
    agg128_kernel<<<gWarp, 128>>>(b1, n);
    // --- layer 2 + log_softmax (fp32 path) ---
    gemm40_kernel<<<gGemm40, 256>>>(W2, n);
    agg40_lsm_kernel<<<gWarp, 128>>>(b2, out, n);
}

// round 9
// speedup vs baseline: 2.0499x; 1.2791x over previous
#include <cuda_runtime.h>
#include <cuda_fp16.h>
#include <mma.h>
#include <math.h>

using namespace nvcuda;

// Fixed problem shape (from reference_code)
#define MAXN 50000
#define MAXE 800000
#define FIN  128
#define FH   128
#define FOUT 40
#define PADN (MAXN + 128)      // row padding for full wmma tiles

// ---------------- device scratch (no allocations allowed) ----------------
__device__ __align__(16) float  g_h[MAXN * FH];    // fp32 h (layer 2 path)
__device__ __align__(16) __half g_hh[PADN * FH];   // fp16 h (layers 0/1 agg)
__device__ __align__(16) float  g_x[MAXN * FH];    // fp32 activations (gemm40)
__device__ __align__(16) __half g_xh[PADN * FH];   // fp16 activations (wmma A)
__device__ float g_dinv[MAXN];
__device__ int   g_cnt[MAXN];
__device__ int   g_rowptr[MAXN + 1];
__device__ int   g_cursor[MAXN];
__device__ int   g_col[MAXE];
__device__ float g_w[MAXE];
__device__ int   g_mode;     // 0=int64, 1=int32, 2=float32, 3=float64
#define SCAN_B 256
#define MAX_BLKS ((MAXN + SCAN_B - 1) / SCAN_B)   // 196
__device__ int   g_bsum[MAX_BLKS];
__device__ int   g_boff[MAX_BLKS];

// ---------------- edge index access, dispatched on detected dtype -------
__device__ __forceinline__ int edge_at(const void* p, int idx, int mode) {
    switch (mode) {
        case 0:  return (int)((const long long*)p)[idx];
        case 1:  return ((const int*)p)[idx];
        case 2:  return (int)((const float*)p)[idx];
        default: return (int)((const double*)p)[idx];
    }
}

// ---------------- prep kernels ----------------
// Convert x -> fp16 g_xh (zero the 128-row pad) and zero g_cnt.
__global__ void convert_x_kernel(const float* __restrict__ x, int n) {
    int i = blockIdx.x * blockDim.x + threadIdx.x;   // half2 index
    int tot = (PADN * FH) / 2;
    int live = (n * FH) / 2;
    if (i < tot) {
        __half2 v = __floats2half2_rn(0.0f, 0.0f);
        if (i < live) {
            float2 f = ((const float2*)x)[i];
            v = __floats2half2_rn(f.x, f.y);
        }
        ((__half2*)g_xh)[i] = v;
    }
    if (i < n) g_cnt[i] = 0;
}

// ONE block, sampled dtype detection (no global atomics).
__global__ void detect_kernel(const unsigned* __restrict__ w, int E, int n) {
    __shared__ int sh[3];
    int t = threadIdx.x;
    unsigned oddnz = 0, evennz = 0, bigint = 0;
    int nsamp = (E < 4096) ? E : 4096;
    for (int k = t; k < nsamp; k += 256) {
        unsigned lo = w[2 * k];
        unsigned hi = w[2 * k + 1];
        oddnz  |= hi;
        evennz |= lo;
        bigint |= (lo >= (unsigned)n || hi >= (unsigned)n) ? 1u : 0u;
    }
    unsigned o  = __any_sync(0xFFFFFFFFu, oddnz != 0);
    unsigned ev = __any_sync(0xFFFFFFFFu, evennz != 0);
    unsigned bg = __any_sync(0xFFFFFFFFu, bigint != 0);
    if (t == 0) { sh[0] = 0; sh[1] = 0; sh[2] = 0; }
    __syncthreads();
    if ((t & 31) == 0) {
        if (o)  atomicOr(&sh[0], 1);
        if (ev) atomicOr(&sh[1], 1);
        if (bg) atomicOr(&sh[2], 1);
    }
    __syncthreads();
    if (t == 0) {
        if (!sh[0])      g_mode = 0;   // int64
        else if (!sh[1]) g_mode = 3;   // float64
        else if (!sh[2]) g_mode = 1;   // int32
        else             g_mode = 2;   // float32
    }
}

__global__ void count_kernel(const void* __restrict__ edges, int E, int n) {
    int i = blockIdx.x * blockDim.x + threadIdx.x;
    if (i < E) {
        int d = edge_at(edges, E + i, g_mode);
        if ((unsigned)d < (unsigned)n) atomicAdd(&g_cnt[d], 1);
    }
}

// fused: per-node dinv + per-block sums for the scan
__global__ void dinv_scanA_kernel(int n) {
    __shared__ int sh[SCAN_B];
    int t = threadIdx.x;
    int i = blockIdx.x * SCAN_B + t;
    int v = (i < n) ? g_cnt[i] : 0;
    if (i < n) g_dinv[i] = rsqrtf((float)(v + 1));  // +1 self-loop
    sh[t] = v;
    __syncthreads();
    for (int off = SCAN_B / 2; off > 0; off >>= 1) {
        if (t < off) sh[t] += sh[t + off];
        __syncthreads();
    }
    if (t == 0) g_bsum[blockIdx.x] = sh[0];
}

__global__ void scanB_kernel(int nb, int n) {
    __shared__ int sh[SCAN_B];
    int t = threadIdx.x;
    int v = (t < nb) ? g_bsum[t] : 0;
    sh[t] = v;
    __syncthreads();
    for (int off = 1; off < SCAN_B; off <<= 1) {
        int add = (t >= off) ? sh[t - off] : 0;
        __syncthreads();
        sh[t] += add;
        __syncthreads();
    }
    if (t < nb) g_boff[t] = sh[t] - v;       // exclusive
    if (t == SCAN_B - 1) g_rowptr[n] = sh[SCAN_B - 1];  // total
}

__global__ void scanC_kernel(int n) {
    __shared__ int sh[SCAN_B];
    int t = threadIdx.x;
    int i = blockIdx.x * SCAN_B + t;
    int v = (i < n) ? g_cnt[i] : 0;
    sh[t] = v;
    __syncthreads();
    for (int off = 1; off < SCAN_B; off <<= 1) {
        int add = (t >= off) ? sh[t - off] : 0;
        __syncthreads();
        sh[t] += add;
        __syncthreads();
    }
    if (i < n) {
        int excl = g_boff[blockIdx.x] + sh[t] - v;
        g_rowptr[i] = excl;
        g_cursor[i] = excl;
    }
}

__global__ void fill_kernel(const void* __restrict__ edges, int E, int n) {
    int i = blockIdx.x * blockDim.x + threadIdx.x;
    if (i < E) {
        int mode = g_mode;
        int s = edge_at(edges, i, mode);
        int d = edge_at(edges, E + i, mode);
        if ((unsigned)s < (unsigned)n && (unsigned)d < (unsigned)n) {
            int pos = atomicAdd(&g_cursor[d], 1);
            g_col[pos] = s;
            g_w[pos] = g_dinv[s] * g_dinv[d];
        }
    }
}

// -------- GEMM (wmma): g_hh = fp16( g_xh[n,128] @ W[128,128] ) -----------
// 8 warps, block tile 128x128, warp tile 32x64 (2x4 m16n16k16 frags),
// K chunks of 64. smem: A 128x80h (20KB) + B 64x144h (18.4KB) = 38.9KB.
#define APAD 80
#define BPAD 144
__global__ __launch_bounds__(256) void gemm128_wmma_kernel(
    const float* __restrict__ W)
{
    __shared__ __half sA[128 * APAD];
    __shared__ __half sB[64 * BPAD];

    int tid = threadIdx.x;
    int w   = tid >> 5;
    int row0 = blockIdx.x * 128;
    int wr = w >> 1;            // 0..3 -> rows 32*wr
    int wc = w & 1;             // 0..1 -> cols 64*wc

    wmma::fragment<wmma::accumulator, 16, 16, 16, __half> c[2][4];
#pragma unroll
    for (int i = 0; i < 2; i++)
#pragma unroll
        for (int j = 0; j < 4; j++) wmma::fill_fragment(c[i][j], __float2half(0.0f));

    for (int k0 = 0; k0 < 128; k0 += 64) {
        // A: 128 rows x 64 halves  (4096 uint32, 16/thread)
        const unsigned* gx = (const unsigned*)g_xh;
#pragma unroll
        for (int l = 0; l < 16; l++) {
            int idx = l * 256 + tid;
            int r  = idx >> 5;          // /32 uint per row-chunk
            int c2 = idx & 31;
            unsigned v = gx[(row0 + r) * 64 + (k0 >> 1) + c2];
            *(unsigned*)&sA[r * APAD + c2 * 2] = v;
        }
        // B: 64 k-rows x 128 cols fp32 -> fp16 (4096 float2, 16/thread)
#pragma unroll
        for (int l = 0; l < 16; l++) {
            int idx = l * 256 + tid;
            int r  = idx >> 6;          // /64 float2 per row
            int c2 = idx & 63;
            float2 f = ((const float2*)W)[(k0 + r) * 64 + c2];
            *(__half2*)&sB[r * BPAD + c2 * 2] = __floats2half2_rn(f.x, f.y);
        }
        __syncthreads();

#pragma unroll
        for (int kk = 0; kk < 64; kk += 16) {
            wmma::fragment<wmma::matrix_a, 16, 16, 16, __half, wmma::row_major> a[2];
            wmma::fragment<wmma::matrix_b, 16, 16, 16, __half, wmma::row_major> bf[4];
#pragma unroll
            for (int i = 0; i < 2; i++)
                wmma::load_matrix_sync(a[i], &sA[(wr * 32 + i * 16) * APAD + kk], APAD);
#pragma unroll
            for (int j = 0; j < 4; j++)
                wmma::load_matrix_sync(bf[j], &sB[kk * BPAD + wc * 64 + j * 16], BPAD);
#pragma unroll
            for (int i = 0; i < 2; i++)
#pragma unroll
                for (int j = 0; j < 4; j++)
                    wmma::mma_sync(c[i][j], a[i], bf[j], c[i][j]);
        }
        __syncthreads();
    }

#pragma unroll
    for (int i = 0; i < 2; i++)
#pragma unroll
        for (int j = 0; j < 4; j++) {
            int row = row0 + wr * 32 + i * 16;
            int col = wc * 64 + j * 16;
            wmma::store_matrix_sync(&g_hh[row * 128 + col], c[i][j], 128,
                                    wmma::mem_row_major);
        }
}

// ---------------- GEMM: g_h[n,40] = g_x[n,128] @ W[128,40] (fp32) --------
#define XPAD 132
__global__ __launch_bounds__(256) void gemm40_kernel(
    const float* __restrict__ W, int n)
{
    __shared__ float sW[128 * 40];
    __shared__ float sX[32 * XPAD];

    int tid = threadIdx.x;
    int row0 = blockIdx.x * 32;

    for (int idx = tid; idx < 128 * 40; idx += 256) sW[idx] = W[idx];
    for (int idx = tid; idx < 32 * 128; idx += 256) {
        int r = idx >> 7;
        int k = idx & 127;
        int row = row0 + r;
        sX[r * XPAD + k] = (row < n) ? g_x[row * 128 + k] : 0.0f;
    }
    __syncthreads();

    int ty = tid >> 3;
    int tx = tid & 7;
    int c0 = tx * 5;

    float acc[5] = {0, 0, 0, 0, 0};
#pragma unroll 4
    for (int k = 0; k < 128; k++) {
        float xv = sX[ty * XPAD + k];
#pragma unroll
        for (int j = 0; j < 5; j++) acc[j] += xv * sW[k * 40 + c0 + j];
    }

    int row = row0 + ty;
    if (row < n) {
#pragma unroll
        for (int j = 0; j < 5; j++) g_h[row * 40 + c0 + j] = acc[j];
    }
}

// ---- aggregation (128-dim): warp/node, fp16 gather, dual write ---------
// g_x (fp32, for gemm40) and g_xh (fp16, for next wmma GEMM)
__global__ __launch_bounds__(128) void agg128_kernel(
    const float* __restrict__ b, int n)
{
    int warp = threadIdx.x >> 5;
    int lane = threadIdx.x & 31;
    int i = blockIdx.x * 4 + warp;
    if (i >= n) return;

    const uint2* __restrict__ hq = (const uint2*)g_hh;  // 4 halves per lane
    float4* x4 = (float4*)g_x;
    uint2*  xh = (uint2*)g_xh;
    const float4* b4 = (const float4*)b;

    float di = g_dinv[i];
    float self_w = di * di;

    uint2 qs = hq[i * 32 + lane];
    float2 s0 = __half22float2(*(const __half2*)&qs.x);
    float2 s1 = __half22float2(*(const __half2*)&qs.y);
    float ax = s0.x * self_w, ay = s0.y * self_w;
    float az = s1.x * self_w, aw = s1.y * self_w;

    int s = g_rowptr[i];
    int e = g_rowptr[i + 1];
    for (int j = s; j < e; j++) {
        int c = g_col[j];
        float wt = g_w[j];
        uint2 q = hq[c * 32 + lane];
        float2 f0 = __half22float2(*(const __half2*)&q.x);
        float2 f1 = __half22float2(*(const __half2*)&q.y);
        ax += wt * f0.x; ay += wt * f0.y;
        az += wt * f1.x; aw += wt * f1.y;
    }
    float4 bv = b4[lane];
    float4 o;
    o.x = fmaxf(ax + bv.x, 0.0f);
    o.y = fmaxf(ay + bv.y, 0.0f);
    o.z = fmaxf(az + bv.z, 0.0f);
    o.w = fmaxf(aw + bv.w, 0.0f);
    x4[i * 32 + lane] = o;
    uint2 oh;
    *(__half2*)&oh.x = __floats2half2_rn(o.x, o.y);
    *(__half2*)&oh.y = __floats2half2_rn(o.z, o.w);
    xh[i * 32 + lane] = oh;
}

// ---------------- final: agg(40) + bias + relu + log_softmax -> out ----
__global__ __launch_bounds__(128) void agg40_lsm_kernel(
    const float* __restrict__ b, float* __restrict__ out, int n)
{
    int warp = threadIdx.x >> 5;
    int lane = threadIdx.x & 31;
    int i = blockIdx.x * 4 + warp;
    if (i >= n) return;

    float y0 = -INFINITY, y1 = -INFINITY;
    bool active = (lane < 20);
    int c0 = lane * 2;

    if (active) {
        float di = g_dinv[i];
        float self_w = di * di;
        const float2* __restrict__ h2 = (const float2*)g_h;
        float2 hv = h2[i * 20 + lane];
        float a0 = hv.x * self_w;
        float a1 = hv.y * self_w;
        int s = g_rowptr[i];
        int e = g_rowptr[i + 1];
        for (int j = s; j < e; j++) {
            int c = g_col[j];
            float wt = g_w[j];
            float2 v = h2[c * 20 + lane];
            a0 += wt * v.x;
            a1 += wt * v.y;
        }
        y0 = fmaxf(a0 + b[c0], 0.0f);
        y1 = fmaxf(a1 + b[c0 + 1], 0.0f);
    }

    float m = fmaxf(y0, y1);
#pragma unroll
    for (int off = 16; off > 0; off >>= 1)
        m = fmaxf(m, __shfl_xor_sync(0xFFFFFFFFu, m, off));

    float se = active ? (expf(y0 - m) + expf(y1 - m)) : 0.0f;
#pragma unroll
    for (int off = 16; off > 0; off >>= 1)
        se += __shfl_xor_sync(0xFFFFFFFFu, se, off);

    float lse = m + logf(se);
    if (active) {
        out[i * 40 + c0]     = y0 - lse;
        out[i * 40 + c0 + 1] = y1 - lse;
    }
}

// ---------------- launch (kernel launches ONLY — capture-safe; ----------
// ---------------- NO __device__ symbol is referenced from host) ---------
extern "C" void kernel_launch(void* const* d_in, const int* in_sizes, int n_in,
                              void* d_out, int out_size) {
    const float* x  = (const float*)d_in[0];
    const void*  ei = d_in[1];
    const float* W0 = (const float*)d_in[2];
    const float* b0 = (const float*)d_in[3];
    const float* W1 = (const float*)d_in[4];
    const float* b1 = (const float*)d_in[5];
    const float* W2 = (const float*)d_in[6];
    const float* b2 = (const float*)d_in[7];
    float* out = (float*)d_out;

    int n = in_sizes[0] / FIN;      // 50000
    int E = in_sizes[1] / 2;        // 800000

    const int TB = 256;
    int gE = (E + TB - 1) / TB;
    int nb = (n + SCAN_B - 1) / SCAN_B;
    int gWarp = (n + 3) / 4;
    int gConv = ((PADN * FH / 2) + TB - 1) / TB;
    int gGemm128 = (n + 127) / 128;          // 391 (pad rows covered)
    int gGemm40  = (n + 31) / 32;

    // --- graph prep (recomputed every replay; deterministic work) ---
    convert_x_kernel<<<gConv, TB>>>(x, n);
    detect_kernel<<<1, 256>>>((const unsigned*)ei, E, n);
    count_kernel<<<gE, TB>>>(ei, E, n);
    dinv_scanA_kernel<<<nb, SCAN_B>>>(n);
    scanB_kernel<<<1, SCAN_B>>>(nb, n);
    scanC_kernel<<<nb, SCAN_B>>>(n);
    fill_kernel<<<gE, TB>>>(ei, E, n);

    // --- layer 0 ---
    gemm128_wmma_kernel<<<gGemm128, 256>>>(W0);
    agg128_kernel<<<gWarp, 128>>>(b0, n);
    // --- layer 1 (A = g_xh, written by agg128) ---
    gemm128_wmma_kernel<<<gGemm128, 256>>>(W1);
    agg128_kernel<<<gWarp, 128>>>(b1, n);
    // --- layer 2 + log_softmax (fp32 path) ---
    gemm40_kernel<<<gGemm40, 256>>>(W2, n);
    agg40_lsm_kernel<<<gWarp, 128>>>(b2, out, n);
}

// round 10
// speedup vs baseline: 2.2129x; 1.0795x over previous
#include <cuda_runtime.h>
#include <cuda_fp16.h>
#include <mma.h>
#include <math.h>

using namespace nvcuda;

// Fixed problem shape (from reference_code)
#define MAXN 50000
#define MAXE 800000
#define FIN  128
#define FH   128
#define FOUT 40
#define PADN (MAXN + 128)      // row padding for full wmma tiles

// ---------------- device scratch (no allocations allowed) ----------------
__device__ __align__(16) __half g_hh[PADN * FH];   // fp16 h (all layers)
__device__ __align__(16) __half g_xh[PADN * FH];   // fp16 activations (wmma A)
__device__ float g_dinv[MAXN];
__device__ int   g_cnt[MAXN];
__device__ int   g_rowptr[MAXN + 1];
__device__ int   g_cursor[MAXN];
__device__ int   g_col[MAXE];
__device__ float g_w[MAXE];
__device__ int   g_mode;     // 0=int64, 1=int32, 2=float32, 3=float64
#define SCAN_B 256
#define MAX_BLKS ((MAXN + SCAN_B - 1) / SCAN_B)   // 196
__device__ int   g_bsum[MAX_BLKS];
__device__ int   g_boff[MAX_BLKS];

// ---------------- edge index access, dispatched on detected dtype -------
__device__ __forceinline__ int edge_at(const void* p, int idx, int mode) {
    switch (mode) {
        case 0:  return (int)((const long long*)p)[idx];
        case 1:  return ((const int*)p)[idx];
        case 2:  return (int)((const float*)p)[idx];
        default: return (int)((const double*)p)[idx];
    }
}

// ---------------- prep kernels ----------------
// Convert x -> fp16 g_xh (zero the 128-row pad) and zero g_cnt.
__global__ void convert_x_kernel(const float* __restrict__ x, int n) {
    int i = blockIdx.x * blockDim.x + threadIdx.x;   // half2 index
    int tot = (PADN * FH) / 2;
    int live = (n * FH) / 2;
    if (i < tot) {
        __half2 v = __floats2half2_rn(0.0f, 0.0f);
        if (i < live) {
            float2 f = ((const float2*)x)[i];
            v = __floats2half2_rn(f.x, f.y);
        }
        ((__half2*)g_xh)[i] = v;
    }
    if (i < n) g_cnt[i] = 0;
}

// ONE block, sampled dtype detection (no global atomics).
__global__ void detect_kernel(const unsigned* __restrict__ w, int E, int n) {
    __shared__ int sh[3];
    int t = threadIdx.x;
    unsigned oddnz = 0, evennz = 0, bigint = 0;
    int nsamp = (E < 4096) ? E : 4096;
    for (int k = t; k < nsamp; k += 256) {
        unsigned lo = w[2 * k];
        unsigned hi = w[2 * k + 1];
        oddnz  |= hi;
        evennz |= lo;
        bigint |= (lo >= (unsigned)n || hi >= (unsigned)n) ? 1u : 0u;
    }
    unsigned o  = __any_sync(0xFFFFFFFFu, oddnz != 0);
    unsigned ev = __any_sync(0xFFFFFFFFu, evennz != 0);
    unsigned bg = __any_sync(0xFFFFFFFFu, bigint != 0);
    if (t == 0) { sh[0] = 0; sh[1] = 0; sh[2] = 0; }
    __syncthreads();
    if ((t & 31) == 0) {
        if (o)  atomicOr(&sh[0], 1);
        if (ev) atomicOr(&sh[1], 1);
        if (bg) atomicOr(&sh[2], 1);
    }
    __syncthreads();
    if (t == 0) {
        if (!sh[0])      g_mode = 0;   // int64
        else if (!sh[1]) g_mode = 3;   // float64
        else if (!sh[2]) g_mode = 1;   // int32
        else             g_mode = 2;   // float32
    }
}

// 2 edges per thread for MLP
__global__ void count_kernel(const void* __restrict__ edges, int E, int n) {
    int i = (blockIdx.x * blockDim.x + threadIdx.x) * 2;
    int mode = g_mode;
    if (i < E) {
        int d0 = edge_at(edges, E + i, mode);
        int d1 = (i + 1 < E) ? edge_at(edges, E + i + 1, mode) : -1;
        if ((unsigned)d0 < (unsigned)n) atomicAdd(&g_cnt[d0], 1);
        if ((unsigned)d1 < (unsigned)n) atomicAdd(&g_cnt[d1], 1);
    }
}

// fused: per-node dinv + per-block sums for the scan
__global__ void dinv_scanA_kernel(int n) {
    __shared__ int sh[SCAN_B];
    int t = threadIdx.x;
    int i = blockIdx.x * SCAN_B + t;
    int v = (i < n) ? g_cnt[i] : 0;
    if (i < n) g_dinv[i] = rsqrtf((float)(v + 1));  // +1 self-loop
    sh[t] = v;
    __syncthreads();
    for (int off = SCAN_B / 2; off > 0; off >>= 1) {
        if (t < off) sh[t] += sh[t + off];
        __syncthreads();
    }
    if (t == 0) g_bsum[blockIdx.x] = sh[0];
}

__global__ void scanB_kernel(int nb, int n) {
    __shared__ int sh[SCAN_B];
    int t = threadIdx.x;
    int v = (t < nb) ? g_bsum[t] : 0;
    sh[t] = v;
    __syncthreads();
    for (int off = 1; off < SCAN_B; off <<= 1) {
        int add = (t >= off) ? sh[t - off] : 0;
        __syncthreads();
        sh[t] += add;
        __syncthreads();
    }
    if (t < nb) g_boff[t] = sh[t] - v;       // exclusive
    if (t == SCAN_B - 1) g_rowptr[n] = sh[SCAN_B - 1];  // total
}

__global__ void scanC_kernel(int n) {
    __shared__ int sh[SCAN_B];
    int t = threadIdx.x;
    int i = blockIdx.x * SCAN_B + t;
    int v = (i < n) ? g_cnt[i] : 0;
    sh[t] = v;
    __syncthreads();
    for (int off = 1; off < SCAN_B; off <<= 1) {
        int add = (t >= off) ? sh[t - off] : 0;
        __syncthreads();
        sh[t] += add;
        __syncthreads();
    }
    if (i < n) {
        int excl = g_boff[blockIdx.x] + sh[t] - v;
        g_rowptr[i] = excl;
        g_cursor[i] = excl;
    }
}

// 2 edges per thread for MLP
__global__ void fill_kernel(const void* __restrict__ edges, int E, int n) {
    int i = (blockIdx.x * blockDim.x + threadIdx.x) * 2;
    int mode = g_mode;
#pragma unroll
    for (int u = 0; u < 2; u++) {
        int idx = i + u;
        if (idx < E) {
            int s = edge_at(edges, idx, mode);
            int d = edge_at(edges, E + idx, mode);
            if ((unsigned)s < (unsigned)n && (unsigned)d < (unsigned)n) {
                int pos = atomicAdd(&g_cursor[d], 1);
                g_col[pos] = s;
                g_w[pos] = g_dinv[s] * g_dinv[d];
            }
        }
    }
}

// -------- GEMM (wmma): g_hh = fp16( g_xh[n,128] @ W[128,128] ) -----------
// 8 warps, block tile 128x128, warp tile 32x64 (2x4 m16n16k16 frags),
// K chunks of 64. smem: A 128x80h (20KB) + B 64x144h (18.4KB) = 38.9KB.
#define APAD 80
#define BPAD 144
__global__ __launch_bounds__(256) void gemm128_wmma_kernel(
    const float* __restrict__ W)
{
    __shared__ __half sA[128 * APAD];
    __shared__ __half sB[64 * BPAD];

    int tid = threadIdx.x;
    int w   = tid >> 5;
    int row0 = blockIdx.x * 128;
    int wr = w >> 1;            // 0..3 -> rows 32*wr
    int wc = w & 1;             // 0..1 -> cols 64*wc

    wmma::fragment<wmma::accumulator, 16, 16, 16, __half> c[2][4];
#pragma unroll
    for (int i = 0; i < 2; i++)
#pragma unroll
        for (int j = 0; j < 4; j++) wmma::fill_fragment(c[i][j], __float2half(0.0f));

    for (int k0 = 0; k0 < 128; k0 += 64) {
        // A: 128 rows x 64 halves  (4096 uint32, 16/thread)
        const unsigned* gx = (const unsigned*)g_xh;
#pragma unroll
        for (int l = 0; l < 16; l++) {
            int idx = l * 256 + tid;
            int r  = idx >> 5;          // /32 uint per row-chunk
            int c2 = idx & 31;
            unsigned v = gx[(row0 + r) * 64 + (k0 >> 1) + c2];
            *(unsigned*)&sA[r * APAD + c2 * 2] = v;
        }
        // B: 64 k-rows x 128 cols fp32 -> fp16 (4096 float2, 16/thread)
#pragma unroll
        for (int l = 0; l < 16; l++) {
            int idx = l * 256 + tid;
            int r  = idx >> 6;          // /64 float2 per row
            int c2 = idx & 63;
            float2 f = ((const float2*)W)[(k0 + r) * 64 + c2];
            *(__half2*)&sB[r * BPAD + c2 * 2] = __floats2half2_rn(f.x, f.y);
        }
        __syncthreads();

#pragma unroll
        for (int kk = 0; kk < 64; kk += 16) {
            wmma::fragment<wmma::matrix_a, 16, 16, 16, __half, wmma::row_major> a[2];
            wmma::fragment<wmma::matrix_b, 16, 16, 16, __half, wmma::row_major> bf[4];
#pragma unroll
            for (int i = 0; i < 2; i++)
                wmma::load_matrix_sync(a[i], &sA[(wr * 32 + i * 16) * APAD + kk], APAD);
#pragma unroll
            for (int j = 0; j < 4; j++)
                wmma::load_matrix_sync(bf[j], &sB[kk * BPAD + wc * 64 + j * 16], BPAD);
#pragma unroll
            for (int i = 0; i < 2; i++)
#pragma unroll
                for (int j = 0; j < 4; j++)
                    wmma::mma_sync(c[i][j], a[i], bf[j], c[i][j]);
        }
        __syncthreads();
    }

#pragma unroll
    for (int i = 0; i < 2; i++)
#pragma unroll
        for (int j = 0; j < 4; j++) {
            int row = row0 + wr * 32 + i * 16;
            int col = wc * 64 + j * 16;
            wmma::store_matrix_sync(&g_hh[row * 128 + col], c[i][j], 128,
                                    wmma::mem_row_major);
        }
}

// ---- GEMM: h40 = fp16( g_xh[n,128] @ W[128,40] ), fp32 compute ---------
// h40 reuses g_hh (layer-1 h is dead by then), laid out [n][40] fp16.
#define XPAD 132
__global__ __launch_bounds__(256) void gemm40_kernel(
    const float* __restrict__ W, int n)
{
    __shared__ float sW[128 * 40];
    __shared__ float sX[32 * XPAD];

    int tid = threadIdx.x;
    int row0 = blockIdx.x * 32;

    for (int idx = tid; idx < 128 * 40; idx += 256) sW[idx] = W[idx];
    // 32 rows x 128 halves = 2048 half2; 8 per thread
    const unsigned* gx = (const unsigned*)g_xh;
    for (int idx = tid; idx < 32 * 64; idx += 256) {
        int r  = idx >> 6;
        int k2 = idx & 63;
        int row = row0 + r;
        float2 f = make_float2(0.0f, 0.0f);
        if (row < n) {
            unsigned v = gx[row * 64 + k2];
            f = __half22float2(*(const __half2*)&v);
        }
        sX[r * XPAD + k2 * 2]     = f.x;
        sX[r * XPAD + k2 * 2 + 1] = f.y;
    }
    __syncthreads();

    int ty = tid >> 3;
    int tx = tid & 7;
    int c0 = tx * 5;

    float acc[5] = {0, 0, 0, 0, 0};
#pragma unroll 4
    for (int k = 0; k < 128; k++) {
        float xv = sX[ty * XPAD + k];
#pragma unroll
        for (int j = 0; j < 5; j++) acc[j] += xv * sW[k * 40 + c0 + j];
    }

    int row = row0 + ty;
    if (row < n) {
        __half* h40 = g_hh;
#pragma unroll
        for (int j = 0; j < 5; j++)
            h40[row * 40 + c0 + j] = __float2half(acc[j]);
    }
}

// ---- aggregation (128-dim): warp/node, fp16 gather, fp16 write ---------
// g_xh = fp16( relu( A_norm @ h + b ) ), fp32 accumulate
__global__ __launch_bounds__(128) void agg128_kernel(
    const float* __restrict__ b, int n)
{
    int warp = threadIdx.x >> 5;
    int lane = threadIdx.x & 31;
    int i = blockIdx.x * 4 + warp;
    if (i >= n) return;

    const uint2* __restrict__ hq = (const uint2*)g_hh;  // 4 halves per lane
    uint2*  xh = (uint2*)g_xh;
    const float4* b4 = (const float4*)b;

    float di = g_dinv[i];
    float self_w = di * di;

    uint2 qs = hq[i * 32 + lane];
    float2 s0 = __half22float2(*(const __half2*)&qs.x);
    float2 s1 = __half22float2(*(const __half2*)&qs.y);
    float ax = s0.x * self_w, ay = s0.y * self_w;
    float az = s1.x * self_w, aw = s1.y * self_w;

    int s = g_rowptr[i];
    int e = g_rowptr[i + 1];
    for (int j = s; j < e; j++) {
        int c = g_col[j];
        float wt = g_w[j];
        uint2 q = hq[c * 32 + lane];
        float2 f0 = __half22float2(*(const __half2*)&q.x);
        float2 f1 = __half22float2(*(const __half2*)&q.y);
        ax += wt * f0.x; ay += wt * f0.y;
        az += wt * f1.x; aw += wt * f1.y;
    }
    float4 bv = b4[lane];
    uint2 oh;
    *(__half2*)&oh.x = __floats2half2_rn(fmaxf(ax + bv.x, 0.0f),
                                         fmaxf(ay + bv.y, 0.0f));
    *(__half2*)&oh.y = __floats2half2_rn(fmaxf(az + bv.z, 0.0f),
                                         fmaxf(aw + bv.w, 0.0f));
    xh[i * 32 + lane] = oh;
}

// ------ final: agg(40, fp16 gather) + bias + relu + log_softmax --------
__global__ __launch_bounds__(128) void agg40_lsm_kernel(
    const float* __restrict__ b, float* __restrict__ out, int n)
{
    int warp = threadIdx.x >> 5;
    int lane = threadIdx.x & 31;
    int i = blockIdx.x * 4 + warp;
    if (i >= n) return;

    float y0 = -INFINITY, y1 = -INFINITY;
    bool active = (lane < 20);
    int c0 = lane * 2;

    if (active) {
        float di = g_dinv[i];
        float self_w = di * di;
        const __half2* __restrict__ h2 = (const __half2*)g_hh;  // [n][20] h2
        float2 hv = __half22float2(h2[i * 20 + lane]);
        float a0 = hv.x * self_w;
        float a1 = hv.y * self_w;
        int s = g_rowptr[i];
        int e = g_rowptr[i + 1];
        for (int j = s; j < e; j++) {
            int c = g_col[j];
            float wt = g_w[j];
            float2 v = __half22float2(h2[c * 20 + lane]);
            a0 += wt * v.x;
            a1 += wt * v.y;
        }
        y0 = fmaxf(a0 + b[c0], 0.0f);
        y1 = fmaxf(a1 + b[c0 + 1], 0.0f);
    }

    float m = fmaxf(y0, y1);
#pragma unroll
    for (int off = 16; off > 0; off >>= 1)
        m = fmaxf(m, __shfl_xor_sync(0xFFFFFFFFu, m, off));

    float se = active ? (expf(y0 - m) + expf(y1 - m)) : 0.0f;
#pragma unroll
    for (int off = 16; off > 0; off >>= 1)
        se += __shfl_xor_sync(0xFFFFFFFFu, se, off);

    float lse = m + logf(se);
    if (active) {
        out[i * 40 + c0]     = y0 - lse;
        out[i * 40 + c0 + 1] = y1 - lse;
    }
}

// ---------------- launch (kernel launches ONLY — capture-safe; ----------
// ---------------- NO __device__ symbol is referenced from host) ---------
extern "C" void kernel_launch(void* const* d_in, const int* in_sizes, int n_in,
                              void* d_out, int out_size) {
    const float* x  = (const float*)d_in[0];
    const void*  ei = d_in[1];
    const float* W0 = (const float*)d_in[2];
    const float* b0 = (const float*)d_in[3];
    const float* W1 = (const float*)d_in[4];
    const float* b1 = (const float*)d_in[5];
    const float* W2 = (const float*)d_in[6];
    const float* b2 = (const float*)d_in[7];
    float* out = (float*)d_out;

    int n = in_sizes[0] / FIN;      // 50000
    int E = in_sizes[1] / 2;        // 800000

    const int TB = 256;
    int gE2 = ((E + 1) / 2 + TB - 1) / TB;
    int nb = (n + SCAN_B - 1) / SCAN_B;
    int gWarp = (n + 3) / 4;
    int gConv = ((PADN * FH / 2) + TB - 1) / TB;
    int gGemm128 = (n + 127) / 128;          // 391 (pad rows covered)
    int gGemm40  = (n + 31) / 32;

    // --- graph prep (recomputed every replay; deterministic work) ---
    convert_x_kernel<<<gConv, TB>>>(x, n);
    detect_kernel<<<1, 256>>>((const unsigned*)ei, E, n);
    count_kernel<<<gE2, TB>>>(ei, E, n);
    dinv_scanA_kernel<<<nb, SCAN_B>>>(n);
    scanB_kernel<<<1, SCAN_B>>>(nb, n);
    scanC_kernel<<<nb, SCAN_B>>>(n);
    fill_kernel<<<gE2, TB>>>(ei, E, n);

    // --- layer 0 ---
    gemm128_wmma_kernel<<<gGemm128, 256>>>(W0);
    agg128_kernel<<<gWarp, 128>>>(b0, n);
    // --- layer 1 (A = g_xh, written by agg128) ---
    gemm128_wmma_kernel<<<gGemm128, 256>>>(W1);
    agg128_kernel<<<gWarp, 128>>>(b1, n);
    // --- layer 2 + log_softmax (fp16-staged, fp32 compute) ---
    gemm40_kernel<<<gGemm40, 256>>>(W2, n);
    agg40_lsm_kernel<<<gWarp, 128>>>(b2, out, n);
}